// round 14
// baseline (speedup 1.0000x reference)
#include <cuda_runtime.h>
#include <cuda_fp16.h>
#include <cstdint>

// ---------------------------------------------------------------------------
// Round 14: R13 fp16 scheme (W fp16-rn, A exact hi+lo fp16, 2 MMAs/chunk,
// one-pass LN, 3-term erf GELU) in R12's shell: TPB=192, 3 CTAs/SM
// (113-reg cap), 32 rows/warp (two m16 tiles) -> B1-LDS amortized over 2x
// rows at 18 warps/SM. Numerics identical to R13.
// ---------------------------------------------------------------------------

typedef unsigned long long u64;

constexpr int TPB  = 192;
constexpr int ROWS = 192;     // 6 warps x 32 rows

// smem word offsets
constexpr int B1F = 0;        // W1 frags: 32 groups * 132 words = 4224
constexpr int B2F = 4224;     // W2 frags: 16 groups * 72 words  = 1152
constexpr int PAR = 5376;
constexpr int P_B1 = 0, P_GM = 64, P_BT = 128, P_B2 = 192, P_WG = 224,
              P_BG = 288, P_BR = 290, P_SG = 304, P_WR = 448; // end 704
constexpr int SMEM_BYTES = (5376 + 704) * 4;   // 24320

static __device__ __forceinline__ void mma_f16(float d[4], const uint32_t a[4],
                                               uint32_t b0, uint32_t b1) {
    asm volatile(
        "mma.sync.aligned.m16n8k16.row.col.f32.f16.f16.f32 "
        "{%0,%1,%2,%3}, {%4,%5,%6,%7}, {%8,%9}, {%0,%1,%2,%3};"
        : "+f"(d[0]), "+f"(d[1]), "+f"(d[2]), "+f"(d[3])
        : "r"(a[0]), "r"(a[1]), "r"(a[2]), "r"(a[3]), "r"(b0), "r"(b1));
}

static __device__ __forceinline__ u64 pk2(float x, float y) {
    u64 r; asm("mov.b64 %0, {%1, %2};" : "=l"(r) : "f"(x), "f"(y)); return r;
}
static __device__ __forceinline__ float2 unpk(u64 v) {
    float2 f; asm("mov.b64 {%0, %1}, %2;" : "=f"(f.x), "=f"(f.y) : "l"(v)); return f;
}
#define FMA2(d, a, b, c) asm("fma.rn.f32x2 %0, %1, %2, %3;" : "=l"(d) : "l"(a), "l"(b), "l"(c))
#define MUL2(d, a, b)    asm("mul.rn.f32x2 %0, %1, %2;"     : "=l"(d) : "l"(a), "l"(b))
#define ADD2(d, a, b)    asm("add.rn.f32x2 %0, %1, %2;"     : "=l"(d) : "l"(a), "l"(b))

struct Split { uint32_t hi, lo; };
// fp16 2-term split: hi = rn(v), lo = rn(v - hi). A side exact to ~2^-22.
static __device__ __forceinline__ Split split2f(float a, float b) {
    Split s;
    __half2 h2 = __floats2half2_rn(a, b);
    float2 hf = __half22float2(h2);
    __half2 l2 = __floats2half2_rn(a - hf.x, b - hf.y);
    s.hi = *reinterpret_cast<uint32_t*>(&h2);
    s.lo = *reinterpret_cast<uint32_t*>(&l2);
    return s;
}
static __device__ __forceinline__ Split split2fp(u64 v2) {
    float2 f = unpk(v2);
    return split2f(f.x, f.y);
}
static __device__ __forceinline__ uint32_t packh2(float a, float b) {
    __half2 h2 = __floats2half2_rn(a, b);
    return *reinterpret_cast<uint32_t*>(&h2);
}

static __device__ __forceinline__ float rcp_fast(float x) {
    float r; asm("rcp.approx.f32 %0, %1;" : "=f"(r) : "f"(x)); return r;
}
static __device__ __forceinline__ float ex2_fast(float x) {
    float r; asm("ex2.approx.f32 %0, %1;" : "=f"(r) : "f"(x)); return r;
}

// packed branchless erf GELU (A&S 7.1.25, |erf err| <= 2.5e-5)
static __device__ __forceinline__ u64 gelu2(u64 v2) {
    u64 av;
    asm("and.b64 %0, %1, %2;" : "=l"(av) : "l"(v2), "l"(0x7FFFFFFF7FFFFFFFull));
    const float IS2 = 0.70710678118654752440f;
    u64 x2;  MUL2(x2, av, pk2(IS2, IS2));
    u64 u;   FMA2(u, x2, pk2(0.47047f, 0.47047f), pk2(1.f, 1.f));
    float2 uf = unpk(u);
    u64 t2 = pk2(rcp_fast(uf.x), rcp_fast(uf.y));
    u64 p;
    FMA2(p, t2, pk2(0.7478556f, 0.7478556f), pk2(-0.0958798f, -0.0958798f));
    FMA2(p, p, t2, pk2(0.3480242f, 0.3480242f));
    MUL2(p, p, t2);
    u64 xx;  MUL2(xx, x2, x2);
    u64 ea;  MUL2(ea, xx, pk2(-1.4426950408889634f, -1.4426950408889634f));
    float2 ef = unpk(ea);
    u64 pe;  MUL2(pe, p, pk2(ex2_fast(ef.x), ex2_fast(ef.y)));
    u64 erf2; FMA2(erf2, pe, pk2(-1.f, -1.f), pk2(1.f, 1.f));
    u64 habs; MUL2(habs, x2, pk2(IS2, IS2));
    u64 hv;   MUL2(hv, v2, pk2(0.5f, 0.5f));
    u64 res;  FMA2(res, habs, erf2, hv);
    return res;
}

__global__ __launch_bounds__(TPB, 3)
void nml_mma_kernel(
    const float* __restrict__ x, const int* __restrict__ regime,
    const float* __restrict__ W1, const float* __restrict__ b1,
    const float* __restrict__ gamma, const float* __restrict__ beta,
    const float* __restrict__ W2, const float* __restrict__ b2,
    const float* __restrict__ Wg, const float* __restrict__ bg,
    const float* __restrict__ Wr, const float* __restrict__ br,
    const float* __restrict__ emb, const float* __restrict__ log_temp,
    float* __restrict__ out, int B)
{
    extern __shared__ float smem[];
    uint32_t* smu = reinterpret_cast<uint32_t*>(smem);
    float* par = smem + PAR;

    const int tid = threadIdx.x;

    // ---- W1 -> fp16 B frags, LDS.128 layout (stride 132 words) -------------
    for (int i = tid; i < 4096; i += TPB) {
        int n = i >> 6, cp = i & 63;
        int ks = cp >> 3, r = cp & 7, sq = r >> 1, j = r & 1;
        int qq = n & 7, nt = n >> 3;
        float2 wv = *reinterpret_cast<const float2*>(W1 + n * 128 + cp * 2);
        smu[B1F + (ks * 4 + sq) * 132 + (qq * 8 + nt) * 2 + j] =
            packh2(wv.x, wv.y);
    }
    // ---- W2 -> fp16 (LDS.64 layout, stride 36 pairs) ------------------------
    for (int i = tid; i < 1024; i += TPB) {
        int n = i >> 5, kpg = i & 31;
        int k2 = kpg >> 3, r = kpg & 7, sq = r & 3, j = r >> 2;
        float2 wv = *reinterpret_cast<const float2*>(W2 + n * 64 + kpg * 2);
        smu[B2F + ((k2 * 4 + sq) * 36 + n) * 2 + j] = packh2(wv.x, wv.y);
    }
    // ---- params --------------------------------------------------------------
    if (tid < 64) {
        par[P_B1 + tid] = b1[tid];
        par[P_GM + tid] = gamma[tid];
        par[P_BT + tid] = beta[tid];
    }
    if (tid < 32) {
        par[P_B2 + tid] = b2[tid];
        par[P_WG + 2 * tid]     = Wg[tid];
        par[P_WG + 2 * tid + 1] = Wg[32 + tid];
    }
    if (tid < 2)  par[P_BG + tid] = 0.7f * bg[tid];
    if (tid < 8)  par[P_BR + tid] = 0.3f * br[tid];
    if (tid < 128) {
        int rr = tid >> 5, c = tid & 31;
        par[P_SG + rr * 36 + c] = 0.5f + 0.2f / (1.0f + expf(-emb[tid]));
    }
    for (int i = tid; i < 256; i += TPB) {
        int rr = i >> 6, rest = i & 63, ch = rest >> 1, sel = rest & 1;
        par[P_WR + rr * 64 + ch * 2 + sel] = Wr[rr * 64 + sel * 32 + ch];
    }
    __syncthreads();

    const int wid  = tid >> 5;
    const int lane = tid & 31;
    const int q    = lane >> 2;
    const int s4   = lane & 3;
    const int q4   = q * 4;
    const int warpRow = blockIdx.x * ROWS + wid * 32;
    const int Bm1 = B - 1;

    // ---- regime prefetch ------------------------------------------------------
    int rrl[2], rrh[2];
#pragma unroll
    for (int t = 0; t < 2; t++) {
        int glo = warpRow + t * 16 + q;
        int ghi = glo + 8;
        rrl[t] = regime[glo > Bm1 ? Bm1 : glo];
        rrh[t] = regime[ghi > Bm1 ? Bm1 : ghi];
    }

    // ======================= layer 1: D1 = X @ W1^T ==========================
    float d1[2][8][4];
#pragma unroll
    for (int t = 0; t < 2; t++)
#pragma unroll
        for (int nt = 0; nt < 8; nt++)
#pragma unroll
            for (int j = 0; j < 4; j++) d1[t][nt][j] = 0.f;

#pragma unroll 2
    for (int ks = 0; ks < 8; ks++) {
        uint32_t Ahi[2][4], Alo[2][4];
#pragma unroll
        for (int t = 0; t < 2; t++) {
            int rlo = warpRow + t * 16 + q;
            int rhi = rlo + 8;
            if (rlo > Bm1) rlo = Bm1;
            if (rhi > Bm1) rhi = Bm1;
            float4 vlo = *reinterpret_cast<const float4*>(
                x + rlo * 128 + ks * 16 + s4 * 4);
            float4 vhi = *reinterpret_cast<const float4*>(
                x + rhi * 128 + ks * 16 + s4 * 4);
            Split s0 = split2f(vlo.x, vlo.y);
            Split s1 = split2f(vhi.x, vhi.y);
            Split s2 = split2f(vlo.z, vlo.w);
            Split s3 = split2f(vhi.z, vhi.w);
            Ahi[t][0] = s0.hi; Alo[t][0] = s0.lo;
            Ahi[t][1] = s1.hi; Alo[t][1] = s1.lo;
            Ahi[t][2] = s2.hi; Alo[t][2] = s2.lo;
            Ahi[t][3] = s3.hi; Alo[t][3] = s3.lo;
        }
        const uint4* bp = reinterpret_cast<const uint4*>(
            smu + B1F + (ks * 4 + s4) * 132);
#pragma unroll
        for (int b = 0; b < 4; b++) {
            uint4 h4 = bp[q4 + b];
            int n0 = 2 * b, n1 = 2 * b + 1;
            mma_f16(d1[0][n0], Ahi[0], h4.x, h4.y);
            mma_f16(d1[1][n0], Ahi[1], h4.x, h4.y);
            mma_f16(d1[0][n1], Ahi[0], h4.z, h4.w);
            mma_f16(d1[1][n1], Ahi[1], h4.z, h4.w);
            mma_f16(d1[0][n0], Alo[0], h4.x, h4.y);
            mma_f16(d1[1][n0], Alo[1], h4.x, h4.y);
            mma_f16(d1[0][n1], Alo[0], h4.z, h4.w);
            mma_f16(d1[1][n1], Alo[1], h4.z, h4.w);
        }
    }

    // ======================= per-tile epilogue ================================
    float temp = expf(log_temp[0]);
    temp = fminf(fmaxf(temp, 0.5f), 5.0f);
    const float it = 1.0f / temp;

    const u64* b1v = reinterpret_cast<const u64*>(par + P_B1);
    const u64* gmv = reinterpret_cast<const u64*>(par + P_GM);
    const u64* btv = reinterpret_cast<const u64*>(par + P_BT);
    const u64* b2v = reinterpret_cast<const u64*>(par + P_B2);
    const u64* wgv = reinterpret_cast<const u64*>(par + P_WG);

#pragma unroll
    for (int t = 0; t < 2; t++) {
        // ---- bias + one-pass sum/sumsq -----------------------------------------
        u64 plo[8], phi[8];
        u64 sl = 0ull, sh = 0ull, ql = 0ull, qh = 0ull;
#pragma unroll
        for (int nt = 0; nt < 8; nt++) {
            u64 bp = b1v[nt * 4 + s4];
            u64 a = pk2(d1[t][nt][0], d1[t][nt][1]);
            u64 b = pk2(d1[t][nt][2], d1[t][nt][3]);
            ADD2(plo[nt], a, bp);
            ADD2(phi[nt], b, bp);
            ADD2(sl, sl, plo[nt]);
            FMA2(ql, plo[nt], plo[nt], ql);
            ADD2(sh, sh, phi[nt]);
            FMA2(qh, phi[nt], phi[nt], qh);
        }
        float2 fsl = unpk(sl), fsh = unpk(sh), fql = unpk(ql), fqh = unpk(qh);
        float slo = fsl.x + fsl.y, shi = fsh.x + fsh.y;
        float sqlo = fql.x + fql.y, sqhi = fqh.x + fqh.y;
#pragma unroll
        for (int d = 1; d <= 2; d <<= 1) {
            slo  += __shfl_xor_sync(0xffffffffu, slo, d);
            shi  += __shfl_xor_sync(0xffffffffu, shi, d);
            sqlo += __shfl_xor_sync(0xffffffffu, sqlo, d);
            sqhi += __shfl_xor_sync(0xffffffffu, sqhi, d);
        }
        float mulo = slo * (1.0f / 64.0f);
        float muhi = shi * (1.0f / 64.0f);
        float varlo = sqlo * (1.0f / 64.0f) - mulo * mulo;
        float varhi = sqhi * (1.0f / 64.0f) - muhi * muhi;
        float rstdlo = rsqrtf(varlo + 1e-5f);
        float rstdhi = rsqrtf(varhi + 1e-5f);
        u64 rl2 = pk2(rstdlo, rstdlo), rh2 = pk2(rstdhi, rstdhi);
        u64 nml = pk2(-mulo, -mulo), nmh = pk2(-muhi, -muhi);

        // ---- scale + GELU (folded bias) ------------------------------------------
#pragma unroll
        for (int nt = 0; nt < 8; nt++) {
            u64 gm = gmv[nt * 4 + s4], bt = btv[nt * 4 + s4];
            u64 grl; MUL2(grl, gm, rl2);
            u64 grh; MUL2(grh, gm, rh2);
            u64 btl; FMA2(btl, grl, nml, bt);
            u64 bth; FMA2(bth, grh, nmh, bt);
            FMA2(plo[nt], plo[nt], grl, btl);
            FMA2(phi[nt], phi[nt], grh, bth);
            plo[nt] = gelu2(plo[nt]);
            phi[nt] = gelu2(phi[nt]);
        }

        // ---- layer 2: per-k2 A-frag split + MMA (2 terms) ------------------------
        float d2[4][4];
#pragma unroll
        for (int nt = 0; nt < 4; nt++)
#pragma unroll
            for (int j = 0; j < 4; j++) d2[nt][j] = 0.f;

#pragma unroll
        for (int k2 = 0; k2 < 4; k2++) {
            uint32_t A2h[4], A2l[4];
            {
                Split s0 = split2fp(plo[2 * k2]);
                Split s1 = split2fp(phi[2 * k2]);
                Split s2 = split2fp(plo[2 * k2 + 1]);
                Split s3 = split2fp(phi[2 * k2 + 1]);
                A2h[0] = s0.hi; A2l[0] = s0.lo;
                A2h[1] = s1.hi; A2l[1] = s1.lo;
                A2h[2] = s2.hi; A2l[2] = s2.lo;
                A2h[3] = s3.hi; A2l[3] = s3.lo;
            }
            const uint2* bp2 = reinterpret_cast<const uint2*>(
                smu + B2F + ((k2 * 4 + s4) * 36 + q) * 2);
            uint2 bh[4];
#pragma unroll
            for (int nt = 0; nt < 4; nt++) bh[nt] = bp2[nt * 8];
#pragma unroll
            for (int nt = 0; nt < 4; nt++) mma_f16(d2[nt], A2h, bh[nt].x, bh[nt].y);
#pragma unroll
            for (int nt = 0; nt < 4; nt++) mma_f16(d2[nt], A2l, bh[nt].x, bh[nt].y);
        }

        // ---- bias + GELU on layer-2 output ----------------------------------------
        u64 qlo[4], qhi2[4];
#pragma unroll
        for (int nt = 0; nt < 4; nt++) {
            u64 bp = b2v[nt * 4 + s4];
            u64 a = pk2(d2[nt][0], d2[nt][1]);
            u64 b = pk2(d2[nt][2], d2[nt][3]);
            ADD2(a, a, bp);
            ADD2(b, b, bp);
            qlo[nt]  = gelu2(a);
            qhi2[nt] = gelu2(b);
        }

        // ---- merged heads -----------------------------------------------------------
        int growlo = warpRow + t * 16 + q;
        int growhi = growlo + 8;
        int rrlo = rrl[t], rrhi = rrh[t];
        const u64* wrlo = reinterpret_cast<const u64*>(par + P_WR + rrlo * 64);
        const u64* wrhi = reinterpret_cast<const u64*>(par + P_WR + rrhi * 64);
        const float* sglo = par + P_SG + rrlo * 36;
        const float* sghi = par + P_SG + rrhi * 36;

        u64 ca2lo = 0ull, cr2lo = 0ull, ca2hi = 0ull, cr2hi = 0ull;
#pragma unroll
        for (int nt = 0; nt < 4; nt++) {
            int ch = nt * 8 + s4 * 2;
            float2 h2  = unpk(qlo[nt]);
            float2 k2v = unpk(qhi2[nt]);
            float2 sl2 = *reinterpret_cast<const float2*>(sglo + ch);
            float2 sh2 = *reinterpret_cast<const float2*>(sghi + ch);
            float e0 = h2.x * sl2.x,  e1 = h2.y * sl2.y;
            float f0 = k2v.x * sh2.x, f1 = k2v.y * sh2.y;
            FMA2(ca2lo, pk2(e0, e0), wgv[ch],     ca2lo);
            FMA2(ca2lo, pk2(e1, e1), wgv[ch + 1], ca2lo);
            FMA2(cr2lo, pk2(h2.x, h2.x), wrlo[ch],     cr2lo);
            FMA2(cr2lo, pk2(h2.y, h2.y), wrlo[ch + 1], cr2lo);
            FMA2(ca2hi, pk2(f0, f0), wgv[ch],     ca2hi);
            FMA2(ca2hi, pk2(f1, f1), wgv[ch + 1], ca2hi);
            FMA2(cr2hi, pk2(k2v.x, k2v.x), wrhi[ch],     cr2hi);
            FMA2(cr2hi, pk2(k2v.y, k2v.y), wrhi[ch + 1], cr2hi);
        }
        float2 calo = unpk(ca2lo), crlo = unpk(cr2lo);
        float2 cahi = unpk(ca2hi), crhi = unpk(cr2hi);
#pragma unroll
        for (int d = 1; d <= 2; d <<= 1) {
            calo.x += __shfl_xor_sync(0xffffffffu, calo.x, d);
            calo.y += __shfl_xor_sync(0xffffffffu, calo.y, d);
            crlo.x += __shfl_xor_sync(0xffffffffu, crlo.x, d);
            crlo.y += __shfl_xor_sync(0xffffffffu, crlo.y, d);
            cahi.x += __shfl_xor_sync(0xffffffffu, cahi.x, d);
            cahi.y += __shfl_xor_sync(0xffffffffu, cahi.y, d);
            crhi.x += __shfl_xor_sync(0xffffffffu, crhi.x, d);
            crhi.y += __shfl_xor_sync(0xffffffffu, crhi.y, d);
        }

        if (s4 == 0) {
            const float bg0 = par[P_BG], bg1 = par[P_BG + 1];
            if (growlo < B) {
                float2 o;
                o.x = (calo.x + 0.3f * crlo.x + bg0 + par[P_BR + rrlo * 2]) * it;
                o.y = (calo.y + 0.3f * crlo.y + bg1 + par[P_BR + rrlo * 2 + 1]) * it;
                reinterpret_cast<float2*>(out)[growlo] = o;
            }
            if (growhi < B) {
                float2 o;
                o.x = (cahi.x + 0.3f * crhi.x + bg0 + par[P_BR + rrhi * 2]) * it;
                o.y = (cahi.y + 0.3f * crhi.y + bg1 + par[P_BR + rrhi * 2 + 1]) * it;
                reinterpret_cast<float2*>(out)[growhi] = o;
            }
        }
    }
}

extern "C" void kernel_launch(void* const* d_in, const int* in_sizes, int n_in,
                              void* d_out, int out_size)
{
    const float* x        = (const float*)d_in[0];
    const int*   regime   = (const int*)  d_in[1];
    const float* W1       = (const float*)d_in[2];
    const float* b1       = (const float*)d_in[3];
    const float* gamma    = (const float*)d_in[4];
    const float* beta     = (const float*)d_in[5];
    const float* W2       = (const float*)d_in[6];
    const float* b2       = (const float*)d_in[7];
    const float* Wg       = (const float*)d_in[8];
    const float* bg       = (const float*)d_in[9];
    const float* Wr       = (const float*)d_in[10];
    const float* br       = (const float*)d_in[11];
    const float* emb      = (const float*)d_in[12];
    const float* log_temp = (const float*)d_in[13];
    float* out = (float*)d_out;

    const int B = in_sizes[1];
    const int grid = (B + ROWS - 1) / ROWS;

    cudaFuncSetAttribute(nml_mma_kernel,
                         cudaFuncAttributeMaxDynamicSharedMemorySize, SMEM_BYTES);
    nml_mma_kernel<<<grid, TPB, SMEM_BYTES>>>(x, regime, W1, b1, gamma, beta,
                                              W2, b2, Wg, bg, Wr, br, emb,
                                              log_temp, out, B);
}

// round 15
// speedup vs baseline: 1.2506x; 1.2506x over previous
#include <cuda_runtime.h>
#include <cuda_fp16.h>
#include <cstdint>

// ---------------------------------------------------------------------------
// Round 15: single-fp16 A everywhere. A (x, h) and W both fp16-rn; ONE MMA
// per k-chunk per accumulator (layer1: 64 MMAs/16rows, layer2: 16).
// Error sources: W quant + A quant, ~4.8e-4 rms total (2x margin to 1e-3).
// Shell = R13: TPB=256, 3 CTAs/SM, 16 rows/warp, one-pass LN, 3-term erf.
// ---------------------------------------------------------------------------

typedef unsigned long long u64;

constexpr int TPB  = 256;
constexpr int ROWS = 128;     // 8 warps x 16 rows

// smem word offsets
constexpr int B1F = 0;        // W1 frags: 32 groups * 132 words = 4224
constexpr int B2F = 4224;     // W2 frags: 16 groups * 72 words  = 1152
constexpr int PAR = 5376;
constexpr int P_B1 = 0, P_GM = 64, P_BT = 128, P_B2 = 192, P_WG = 224,
              P_BG = 288, P_BR = 290, P_SG = 304, P_WR = 448; // end 704
constexpr int SMEM_BYTES = (5376 + 704) * 4;   // 24320

static __device__ __forceinline__ void mma_f16(float d[4], const uint32_t a[4],
                                               uint32_t b0, uint32_t b1) {
    asm volatile(
        "mma.sync.aligned.m16n8k16.row.col.f32.f16.f16.f32 "
        "{%0,%1,%2,%3}, {%4,%5,%6,%7}, {%8,%9}, {%0,%1,%2,%3};"
        : "+f"(d[0]), "+f"(d[1]), "+f"(d[2]), "+f"(d[3])
        : "r"(a[0]), "r"(a[1]), "r"(a[2]), "r"(a[3]), "r"(b0), "r"(b1));
}

static __device__ __forceinline__ u64 pk2(float x, float y) {
    u64 r; asm("mov.b64 %0, {%1, %2};" : "=l"(r) : "f"(x), "f"(y)); return r;
}
static __device__ __forceinline__ float2 unpk(u64 v) {
    float2 f; asm("mov.b64 {%0, %1}, %2;" : "=f"(f.x), "=f"(f.y) : "l"(v)); return f;
}
#define FMA2(d, a, b, c) asm("fma.rn.f32x2 %0, %1, %2, %3;" : "=l"(d) : "l"(a), "l"(b), "l"(c))
#define MUL2(d, a, b)    asm("mul.rn.f32x2 %0, %1, %2;"     : "=l"(d) : "l"(a), "l"(b))
#define ADD2(d, a, b)    asm("add.rn.f32x2 %0, %1, %2;"     : "=l"(d) : "l"(a), "l"(b))

// single fp16 pack (A and W)
static __device__ __forceinline__ uint32_t packh2(float a, float b) {
    __half2 h2 = __floats2half2_rn(a, b);
    return *reinterpret_cast<uint32_t*>(&h2);
}
static __device__ __forceinline__ uint32_t packh2p(u64 v2) {
    float2 f = unpk(v2);
    return packh2(f.x, f.y);
}

static __device__ __forceinline__ float rcp_fast(float x) {
    float r; asm("rcp.approx.f32 %0, %1;" : "=f"(r) : "f"(x)); return r;
}
static __device__ __forceinline__ float ex2_fast(float x) {
    float r; asm("ex2.approx.f32 %0, %1;" : "=f"(r) : "f"(x)); return r;
}

// packed branchless erf GELU (A&S 7.1.25, |erf err| <= 2.5e-5)
static __device__ __forceinline__ u64 gelu2(u64 v2) {
    u64 av;
    asm("and.b64 %0, %1, %2;" : "=l"(av) : "l"(v2), "l"(0x7FFFFFFF7FFFFFFFull));
    const float IS2 = 0.70710678118654752440f;
    u64 x2;  MUL2(x2, av, pk2(IS2, IS2));
    u64 u;   FMA2(u, x2, pk2(0.47047f, 0.47047f), pk2(1.f, 1.f));
    float2 uf = unpk(u);
    u64 t2 = pk2(rcp_fast(uf.x), rcp_fast(uf.y));
    u64 p;
    FMA2(p, t2, pk2(0.7478556f, 0.7478556f), pk2(-0.0958798f, -0.0958798f));
    FMA2(p, p, t2, pk2(0.3480242f, 0.3480242f));
    MUL2(p, p, t2);
    u64 xx;  MUL2(xx, x2, x2);
    u64 ea;  MUL2(ea, xx, pk2(-1.4426950408889634f, -1.4426950408889634f));
    float2 ef = unpk(ea);
    u64 pe;  MUL2(pe, p, pk2(ex2_fast(ef.x), ex2_fast(ef.y)));
    u64 erf2; FMA2(erf2, pe, pk2(-1.f, -1.f), pk2(1.f, 1.f));
    u64 habs; MUL2(habs, x2, pk2(IS2, IS2));
    u64 hv;   MUL2(hv, v2, pk2(0.5f, 0.5f));
    u64 res;  FMA2(res, habs, erf2, hv);
    return res;
}

__global__ __launch_bounds__(TPB, 3)
void nml_mma_kernel(
    const float* __restrict__ x, const int* __restrict__ regime,
    const float* __restrict__ W1, const float* __restrict__ b1,
    const float* __restrict__ gamma, const float* __restrict__ beta,
    const float* __restrict__ W2, const float* __restrict__ b2,
    const float* __restrict__ Wg, const float* __restrict__ bg,
    const float* __restrict__ Wr, const float* __restrict__ br,
    const float* __restrict__ emb, const float* __restrict__ log_temp,
    float* __restrict__ out, int B)
{
    extern __shared__ float smem[];
    uint32_t* smu = reinterpret_cast<uint32_t*>(smem);
    float* par = smem + PAR;

    const int tid = threadIdx.x;

    // ---- W1 -> fp16 B frags, LDS.128 layout (stride 132 words) -------------
    for (int i = tid; i < 4096; i += TPB) {
        int n = i >> 6, cp = i & 63;
        int ks = cp >> 3, r = cp & 7, sq = r >> 1, j = r & 1;
        int qq = n & 7, nt = n >> 3;
        float2 wv = *reinterpret_cast<const float2*>(W1 + n * 128 + cp * 2);
        smu[B1F + (ks * 4 + sq) * 132 + (qq * 8 + nt) * 2 + j] =
            packh2(wv.x, wv.y);
    }
    // ---- W2 -> fp16 (LDS.64 layout, stride 36 pairs) ------------------------
    for (int i = tid; i < 1024; i += TPB) {
        int n = i >> 5, kpg = i & 31;
        int k2 = kpg >> 3, r = kpg & 7, sq = r & 3, j = r >> 2;
        float2 wv = *reinterpret_cast<const float2*>(W2 + n * 64 + kpg * 2);
        smu[B2F + ((k2 * 4 + sq) * 36 + n) * 2 + j] = packh2(wv.x, wv.y);
    }
    // ---- params --------------------------------------------------------------
    if (tid < 64) {
        par[P_B1 + tid] = b1[tid];
        par[P_GM + tid] = gamma[tid];
        par[P_BT + tid] = beta[tid];
    }
    if (tid < 32) {
        par[P_B2 + tid] = b2[tid];
        par[P_WG + 2 * tid]     = Wg[tid];
        par[P_WG + 2 * tid + 1] = Wg[32 + tid];
    }
    if (tid < 2)  par[P_BG + tid] = 0.7f * bg[tid];
    if (tid < 8)  par[P_BR + tid] = 0.3f * br[tid];
    if (tid < 128) {
        int rr = tid >> 5, c = tid & 31;
        par[P_SG + rr * 36 + c] = 0.5f + 0.2f / (1.0f + expf(-emb[tid]));
    }
    {
        int rr = tid >> 6, rest = tid & 63, ch = rest >> 1, sel = rest & 1;
        par[P_WR + rr * 64 + ch * 2 + sel] = Wr[rr * 64 + sel * 32 + ch];
    }
    __syncthreads();

    const int wid  = tid >> 5;
    const int lane = tid & 31;
    const int q    = lane >> 2;
    const int s4   = lane & 3;
    const int q4   = q * 4;
    const int warpRow = blockIdx.x * ROWS + wid * 16;
    const int Bm1 = B - 1;

    // ---- rows + regime prefetch ----------------------------------------------
    int growlo = warpRow + q;
    int growhi = growlo + 8;
    int rloC = growlo > Bm1 ? Bm1 : growlo;
    int rhiC = growhi > Bm1 ? Bm1 : growhi;
    const int rrlo = regime[rloC];
    const int rrhi = regime[rhiC];
    const float* xlo = x + rloC * 128 + s4 * 4;
    const float* xhi = x + rhiC * 128 + s4 * 4;

    // ======================= layer 1: D1 = X @ W1^T ==========================
    float d1[8][4];
#pragma unroll
    for (int nt = 0; nt < 8; nt++)
#pragma unroll
        for (int j = 0; j < 4; j++) d1[nt][j] = 0.f;

#pragma unroll 2
    for (int ks = 0; ks < 8; ks++) {
        float4 vlo = *reinterpret_cast<const float4*>(xlo + ks * 16);
        float4 vhi = *reinterpret_cast<const float4*>(xhi + ks * 16);
        uint32_t A[4];
        A[0] = packh2(vlo.x, vlo.y);
        A[1] = packh2(vhi.x, vhi.y);
        A[2] = packh2(vlo.z, vlo.w);
        A[3] = packh2(vhi.z, vhi.w);
        const uint4* bp = reinterpret_cast<const uint4*>(
            smu + B1F + (ks * 4 + s4) * 132);
#pragma unroll
        for (int b = 0; b < 4; b++) {
            uint4 h4 = bp[q4 + b];
            mma_f16(d1[2 * b],     A, h4.x, h4.y);
            mma_f16(d1[2 * b + 1], A, h4.z, h4.w);
        }
    }

    // ======================= epilogue =========================================
    float temp = expf(log_temp[0]);
    temp = fminf(fmaxf(temp, 0.5f), 5.0f);
    const float it = 1.0f / temp;

    const u64* b1v = reinterpret_cast<const u64*>(par + P_B1);
    const u64* gmv = reinterpret_cast<const u64*>(par + P_GM);
    const u64* btv = reinterpret_cast<const u64*>(par + P_BT);
    const u64* b2v = reinterpret_cast<const u64*>(par + P_B2);
    const u64* wgv = reinterpret_cast<const u64*>(par + P_WG);

    // ---- bias + one-pass sum/sumsq ---------------------------------------------
    u64 plo[8], phi[8];
    u64 sl = 0ull, sh = 0ull, ql = 0ull, qh = 0ull;
#pragma unroll
    for (int nt = 0; nt < 8; nt++) {
        u64 bp = b1v[nt * 4 + s4];
        u64 a = pk2(d1[nt][0], d1[nt][1]);
        u64 b = pk2(d1[nt][2], d1[nt][3]);
        ADD2(plo[nt], a, bp);
        ADD2(phi[nt], b, bp);
        ADD2(sl, sl, plo[nt]);
        FMA2(ql, plo[nt], plo[nt], ql);
        ADD2(sh, sh, phi[nt]);
        FMA2(qh, phi[nt], phi[nt], qh);
    }
    float2 fsl = unpk(sl), fsh = unpk(sh), fql = unpk(ql), fqh = unpk(qh);
    float slo = fsl.x + fsl.y, shi = fsh.x + fsh.y;
    float sqlo = fql.x + fql.y, sqhi = fqh.x + fqh.y;
#pragma unroll
    for (int d = 1; d <= 2; d <<= 1) {
        slo  += __shfl_xor_sync(0xffffffffu, slo, d);
        shi  += __shfl_xor_sync(0xffffffffu, shi, d);
        sqlo += __shfl_xor_sync(0xffffffffu, sqlo, d);
        sqhi += __shfl_xor_sync(0xffffffffu, sqhi, d);
    }
    float mulo = slo * (1.0f / 64.0f);
    float muhi = shi * (1.0f / 64.0f);
    float varlo = sqlo * (1.0f / 64.0f) - mulo * mulo;
    float varhi = sqhi * (1.0f / 64.0f) - muhi * muhi;
    float rstdlo = rsqrtf(varlo + 1e-5f);
    float rstdhi = rsqrtf(varhi + 1e-5f);
    u64 rl2 = pk2(rstdlo, rstdlo), rh2 = pk2(rstdhi, rstdhi);
    u64 nml = pk2(-mulo, -mulo), nmh = pk2(-muhi, -muhi);

    // ---- scale + GELU (folded bias) ----------------------------------------------
#pragma unroll
    for (int nt = 0; nt < 8; nt++) {
        u64 gm = gmv[nt * 4 + s4], bt = btv[nt * 4 + s4];
        u64 grl; MUL2(grl, gm, rl2);
        u64 grh; MUL2(grh, gm, rh2);
        u64 btl; FMA2(btl, grl, nml, bt);
        u64 bth; FMA2(bth, grh, nmh, bt);
        FMA2(plo[nt], plo[nt], grl, btl);
        FMA2(phi[nt], phi[nt], grh, bth);
        plo[nt] = gelu2(plo[nt]);
        phi[nt] = gelu2(phi[nt]);
    }

    // ---- layer 2: per-k2 A-frag pack + MMA (1 term) -------------------------------
    float d2[4][4];
#pragma unroll
    for (int nt = 0; nt < 4; nt++)
#pragma unroll
        for (int j = 0; j < 4; j++) d2[nt][j] = 0.f;

#pragma unroll
    for (int k2 = 0; k2 < 4; k2++) {
        uint32_t A2[4];
        A2[0] = packh2p(plo[2 * k2]);
        A2[1] = packh2p(phi[2 * k2]);
        A2[2] = packh2p(plo[2 * k2 + 1]);
        A2[3] = packh2p(phi[2 * k2 + 1]);
        const uint2* bp2 = reinterpret_cast<const uint2*>(
            smu + B2F + ((k2 * 4 + s4) * 36 + q) * 2);
        uint2 bh[4];
#pragma unroll
        for (int nt = 0; nt < 4; nt++) bh[nt] = bp2[nt * 8];
#pragma unroll
        for (int nt = 0; nt < 4; nt++) mma_f16(d2[nt], A2, bh[nt].x, bh[nt].y);
    }

    // ---- bias + GELU on layer-2 output ---------------------------------------------
    u64 qlo[4], qhi2[4];
#pragma unroll
    for (int nt = 0; nt < 4; nt++) {
        u64 bp = b2v[nt * 4 + s4];
        u64 a = pk2(d2[nt][0], d2[nt][1]);
        u64 b = pk2(d2[nt][2], d2[nt][3]);
        ADD2(a, a, bp);
        ADD2(b, b, bp);
        qlo[nt]  = gelu2(a);
        qhi2[nt] = gelu2(b);
    }

    // ---- merged heads ----------------------------------------------------------------
    const u64* wrlo = reinterpret_cast<const u64*>(par + P_WR + rrlo * 64);
    const u64* wrhi = reinterpret_cast<const u64*>(par + P_WR + rrhi * 64);
    const float* sglo = par + P_SG + rrlo * 36;
    const float* sghi = par + P_SG + rrhi * 36;

    u64 ca2lo = 0ull, cr2lo = 0ull, ca2hi = 0ull, cr2hi = 0ull;
#pragma unroll
    for (int nt = 0; nt < 4; nt++) {
        int ch = nt * 8 + s4 * 2;
        float2 h2  = unpk(qlo[nt]);
        float2 k2v = unpk(qhi2[nt]);
        float2 sl2 = *reinterpret_cast<const float2*>(sglo + ch);
        float2 sh2 = *reinterpret_cast<const float2*>(sghi + ch);
        float e0 = h2.x * sl2.x,  e1 = h2.y * sl2.y;
        float f0 = k2v.x * sh2.x, f1 = k2v.y * sh2.y;
        FMA2(ca2lo, pk2(e0, e0), wgv[ch],     ca2lo);
        FMA2(ca2lo, pk2(e1, e1), wgv[ch + 1], ca2lo);
        FMA2(cr2lo, pk2(h2.x, h2.x), wrlo[ch],     cr2lo);
        FMA2(cr2lo, pk2(h2.y, h2.y), wrlo[ch + 1], cr2lo);
        FMA2(ca2hi, pk2(f0, f0), wgv[ch],     ca2hi);
        FMA2(ca2hi, pk2(f1, f1), wgv[ch + 1], ca2hi);
        FMA2(cr2hi, pk2(k2v.x, k2v.x), wrhi[ch],     cr2hi);
        FMA2(cr2hi, pk2(k2v.y, k2v.y), wrhi[ch + 1], cr2hi);
    }
    float2 calo = unpk(ca2lo), crlo = unpk(cr2lo);
    float2 cahi = unpk(ca2hi), crhi = unpk(cr2hi);
#pragma unroll
    for (int d = 1; d <= 2; d <<= 1) {
        calo.x += __shfl_xor_sync(0xffffffffu, calo.x, d);
        calo.y += __shfl_xor_sync(0xffffffffu, calo.y, d);
        crlo.x += __shfl_xor_sync(0xffffffffu, crlo.x, d);
        crlo.y += __shfl_xor_sync(0xffffffffu, crlo.y, d);
        cahi.x += __shfl_xor_sync(0xffffffffu, cahi.x, d);
        cahi.y += __shfl_xor_sync(0xffffffffu, cahi.y, d);
        crhi.x += __shfl_xor_sync(0xffffffffu, crhi.x, d);
        crhi.y += __shfl_xor_sync(0xffffffffu, crhi.y, d);
    }

    if (s4 == 0) {
        const float bg0 = par[P_BG], bg1 = par[P_BG + 1];
        if (growlo < B) {
            float2 o;
            o.x = (calo.x + 0.3f * crlo.x + bg0 + par[P_BR + rrlo * 2]) * it;
            o.y = (calo.y + 0.3f * crlo.y + bg1 + par[P_BR + rrlo * 2 + 1]) * it;
            reinterpret_cast<float2*>(out)[growlo] = o;
        }
        if (growhi < B) {
            float2 o;
            o.x = (cahi.x + 0.3f * crhi.x + bg0 + par[P_BR + rrhi * 2]) * it;
            o.y = (cahi.y + 0.3f * crhi.y + bg1 + par[P_BR + rrhi * 2 + 1]) * it;
            reinterpret_cast<float2*>(out)[growhi] = o;
        }
    }
}

extern "C" void kernel_launch(void* const* d_in, const int* in_sizes, int n_in,
                              void* d_out, int out_size)
{
    const float* x        = (const float*)d_in[0];
    const int*   regime   = (const int*)  d_in[1];
    const float* W1       = (const float*)d_in[2];
    const float* b1       = (const float*)d_in[3];
    const float* gamma    = (const float*)d_in[4];
    const float* beta     = (const float*)d_in[5];
    const float* W2       = (const float*)d_in[6];
    const float* b2       = (const float*)d_in[7];
    const float* Wg       = (const float*)d_in[8];
    const float* bg       = (const float*)d_in[9];
    const float* Wr       = (const float*)d_in[10];
    const float* br       = (const float*)d_in[11];
    const float* emb      = (const float*)d_in[12];
    const float* log_temp = (const float*)d_in[13];
    float* out = (float*)d_out;

    const int B = in_sizes[1];
    const int grid = (B + ROWS - 1) / ROWS;

    cudaFuncSetAttribute(nml_mma_kernel,
                         cudaFuncAttributeMaxDynamicSharedMemorySize, SMEM_BYTES);
    nml_mma_kernel<<<grid, TPB, SMEM_BYTES>>>(x, regime, W1, b1, gamma, beta,
                                              W2, b2, Wg, bg, Wr, br, emb,
                                              log_temp, out, B);
}

// round 16
// speedup vs baseline: 1.3451x; 1.0756x over previous
#include <cuda_runtime.h>
#include <cuda_fp16.h>
#include <cstdint>

// ---------------------------------------------------------------------------
// Round 16: R15 single-fp16 scheme (W and A fp16-rn, 1 MMA per k-chunk,
// one-pass LN, 3-term erf GELU, merged g+g2 head) at 32 rows/warp:
// TPB=256, __launch_bounds__(256,2) -> 128-reg cap (proven spill-free shape),
// two m16 tiles per warp -> B1-fragment LDS amortized over 2x rows.
// ---------------------------------------------------------------------------

typedef unsigned long long u64;

constexpr int TPB  = 256;
constexpr int ROWS = 256;     // 8 warps x 32 rows

// smem word offsets
constexpr int B1F = 0;        // W1 frags: 32 groups * 132 words = 4224
constexpr int B2F = 4224;     // W2 frags: 16 groups * 72 words  = 1152
constexpr int PAR = 5376;
constexpr int P_B1 = 0, P_GM = 64, P_BT = 128, P_B2 = 192, P_WG = 224,
              P_BG = 288, P_BR = 290, P_SG = 304, P_WR = 448; // end 704
constexpr int SMEM_BYTES = (5376 + 704) * 4;   // 24320

static __device__ __forceinline__ void mma_f16(float d[4], const uint32_t a[4],
                                               uint32_t b0, uint32_t b1) {
    asm volatile(
        "mma.sync.aligned.m16n8k16.row.col.f32.f16.f16.f32 "
        "{%0,%1,%2,%3}, {%4,%5,%6,%7}, {%8,%9}, {%0,%1,%2,%3};"
        : "+f"(d[0]), "+f"(d[1]), "+f"(d[2]), "+f"(d[3])
        : "r"(a[0]), "r"(a[1]), "r"(a[2]), "r"(a[3]), "r"(b0), "r"(b1));
}

static __device__ __forceinline__ u64 pk2(float x, float y) {
    u64 r; asm("mov.b64 %0, {%1, %2};" : "=l"(r) : "f"(x), "f"(y)); return r;
}
static __device__ __forceinline__ float2 unpk(u64 v) {
    float2 f; asm("mov.b64 {%0, %1}, %2;" : "=f"(f.x), "=f"(f.y) : "l"(v)); return f;
}
#define FMA2(d, a, b, c) asm("fma.rn.f32x2 %0, %1, %2, %3;" : "=l"(d) : "l"(a), "l"(b), "l"(c))
#define MUL2(d, a, b)    asm("mul.rn.f32x2 %0, %1, %2;"     : "=l"(d) : "l"(a), "l"(b))
#define ADD2(d, a, b)    asm("add.rn.f32x2 %0, %1, %2;"     : "=l"(d) : "l"(a), "l"(b))

// single fp16 pack (A and W)
static __device__ __forceinline__ uint32_t packh2(float a, float b) {
    __half2 h2 = __floats2half2_rn(a, b);
    return *reinterpret_cast<uint32_t*>(&h2);
}
static __device__ __forceinline__ uint32_t packh2p(u64 v2) {
    float2 f = unpk(v2);
    return packh2(f.x, f.y);
}

static __device__ __forceinline__ float rcp_fast(float x) {
    float r; asm("rcp.approx.f32 %0, %1;" : "=f"(r) : "f"(x)); return r;
}
static __device__ __forceinline__ float ex2_fast(float x) {
    float r; asm("ex2.approx.f32 %0, %1;" : "=f"(r) : "f"(x)); return r;
}

// packed branchless erf GELU (A&S 7.1.25, |erf err| <= 2.5e-5)
static __device__ __forceinline__ u64 gelu2(u64 v2) {
    u64 av;
    asm("and.b64 %0, %1, %2;" : "=l"(av) : "l"(v2), "l"(0x7FFFFFFF7FFFFFFFull));
    const float IS2 = 0.70710678118654752440f;
    u64 x2;  MUL2(x2, av, pk2(IS2, IS2));
    u64 u;   FMA2(u, x2, pk2(0.47047f, 0.47047f), pk2(1.f, 1.f));
    float2 uf = unpk(u);
    u64 t2 = pk2(rcp_fast(uf.x), rcp_fast(uf.y));
    u64 p;
    FMA2(p, t2, pk2(0.7478556f, 0.7478556f), pk2(-0.0958798f, -0.0958798f));
    FMA2(p, p, t2, pk2(0.3480242f, 0.3480242f));
    MUL2(p, p, t2);
    u64 xx;  MUL2(xx, x2, x2);
    u64 ea;  MUL2(ea, xx, pk2(-1.4426950408889634f, -1.4426950408889634f));
    float2 ef = unpk(ea);
    u64 pe;  MUL2(pe, p, pk2(ex2_fast(ef.x), ex2_fast(ef.y)));
    u64 erf2; FMA2(erf2, pe, pk2(-1.f, -1.f), pk2(1.f, 1.f));
    u64 habs; MUL2(habs, x2, pk2(IS2, IS2));
    u64 hv;   MUL2(hv, v2, pk2(0.5f, 0.5f));
    u64 res;  FMA2(res, habs, erf2, hv);
    return res;
}

__global__ __launch_bounds__(TPB, 2)
void nml_mma_kernel(
    const float* __restrict__ x, const int* __restrict__ regime,
    const float* __restrict__ W1, const float* __restrict__ b1,
    const float* __restrict__ gamma, const float* __restrict__ beta,
    const float* __restrict__ W2, const float* __restrict__ b2,
    const float* __restrict__ Wg, const float* __restrict__ bg,
    const float* __restrict__ Wr, const float* __restrict__ br,
    const float* __restrict__ emb, const float* __restrict__ log_temp,
    float* __restrict__ out, int B)
{
    extern __shared__ float smem[];
    uint32_t* smu = reinterpret_cast<uint32_t*>(smem);
    float* par = smem + PAR;

    const int tid = threadIdx.x;

    // ---- W1 -> fp16 B frags, LDS.128 layout (stride 132 words) -------------
    for (int i = tid; i < 4096; i += TPB) {
        int n = i >> 6, cp = i & 63;
        int ks = cp >> 3, r = cp & 7, sq = r >> 1, j = r & 1;
        int qq = n & 7, nt = n >> 3;
        float2 wv = *reinterpret_cast<const float2*>(W1 + n * 128 + cp * 2);
        smu[B1F + (ks * 4 + sq) * 132 + (qq * 8 + nt) * 2 + j] =
            packh2(wv.x, wv.y);
    }
    // ---- W2 -> fp16 (LDS.64 layout, stride 36 pairs) ------------------------
    for (int i = tid; i < 1024; i += TPB) {
        int n = i >> 5, kpg = i & 31;
        int k2 = kpg >> 3, r = kpg & 7, sq = r & 3, j = r >> 2;
        float2 wv = *reinterpret_cast<const float2*>(W2 + n * 64 + kpg * 2);
        smu[B2F + ((k2 * 4 + sq) * 36 + n) * 2 + j] = packh2(wv.x, wv.y);
    }
    // ---- params --------------------------------------------------------------
    if (tid < 64) {
        par[P_B1 + tid] = b1[tid];
        par[P_GM + tid] = gamma[tid];
        par[P_BT + tid] = beta[tid];
    }
    if (tid < 32) {
        par[P_B2 + tid] = b2[tid];
        par[P_WG + 2 * tid]     = Wg[tid];
        par[P_WG + 2 * tid + 1] = Wg[32 + tid];
    }
    if (tid < 2)  par[P_BG + tid] = 0.7f * bg[tid];
    if (tid < 8)  par[P_BR + tid] = 0.3f * br[tid];
    if (tid < 128) {
        int rr = tid >> 5, c = tid & 31;
        par[P_SG + rr * 36 + c] = 0.5f + 0.2f / (1.0f + expf(-emb[tid]));
    }
    {
        int rr = tid >> 6, rest = tid & 63, ch = rest >> 1, sel = rest & 1;
        par[P_WR + rr * 64 + ch * 2 + sel] = Wr[rr * 64 + sel * 32 + ch];
    }
    __syncthreads();

    const int wid  = tid >> 5;
    const int lane = tid & 31;
    const int q    = lane >> 2;
    const int s4   = lane & 3;
    const int q4   = q * 4;
    const int warpRow = blockIdx.x * ROWS + wid * 32;
    const int Bm1 = B - 1;

    // ---- regime prefetch ------------------------------------------------------
    int rrl[2], rrh[2];
#pragma unroll
    for (int t = 0; t < 2; t++) {
        int glo = warpRow + t * 16 + q;
        int ghi = glo + 8;
        rrl[t] = regime[glo > Bm1 ? Bm1 : glo];
        rrh[t] = regime[ghi > Bm1 ? Bm1 : ghi];
    }

    // ======================= layer 1: D1 = X @ W1^T ==========================
    float d1[2][8][4];
#pragma unroll
    for (int t = 0; t < 2; t++)
#pragma unroll
        for (int nt = 0; nt < 8; nt++)
#pragma unroll
            for (int j = 0; j < 4; j++) d1[t][nt][j] = 0.f;

#pragma unroll 2
    for (int ks = 0; ks < 8; ks++) {
        uint32_t A[2][4];
#pragma unroll
        for (int t = 0; t < 2; t++) {
            int rlo = warpRow + t * 16 + q;
            int rhi = rlo + 8;
            if (rlo > Bm1) rlo = Bm1;
            if (rhi > Bm1) rhi = Bm1;
            float4 vlo = *reinterpret_cast<const float4*>(
                x + rlo * 128 + ks * 16 + s4 * 4);
            float4 vhi = *reinterpret_cast<const float4*>(
                x + rhi * 128 + ks * 16 + s4 * 4);
            A[t][0] = packh2(vlo.x, vlo.y);
            A[t][1] = packh2(vhi.x, vhi.y);
            A[t][2] = packh2(vlo.z, vlo.w);
            A[t][3] = packh2(vhi.z, vhi.w);
        }
        const uint4* bp = reinterpret_cast<const uint4*>(
            smu + B1F + (ks * 4 + s4) * 132);
#pragma unroll
        for (int b = 0; b < 4; b++) {
            uint4 h4 = bp[q4 + b];
            int n0 = 2 * b, n1 = 2 * b + 1;
            mma_f16(d1[0][n0], A[0], h4.x, h4.y);
            mma_f16(d1[1][n0], A[1], h4.x, h4.y);
            mma_f16(d1[0][n1], A[0], h4.z, h4.w);
            mma_f16(d1[1][n1], A[1], h4.z, h4.w);
        }
    }

    // ======================= per-tile epilogue ================================
    float temp = expf(log_temp[0]);
    temp = fminf(fmaxf(temp, 0.5f), 5.0f);
    const float it = 1.0f / temp;

    const u64* b1v = reinterpret_cast<const u64*>(par + P_B1);
    const u64* gmv = reinterpret_cast<const u64*>(par + P_GM);
    const u64* btv = reinterpret_cast<const u64*>(par + P_BT);
    const u64* b2v = reinterpret_cast<const u64*>(par + P_B2);
    const u64* wgv = reinterpret_cast<const u64*>(par + P_WG);

#pragma unroll
    for (int t = 0; t < 2; t++) {
        // ---- bias + one-pass sum/sumsq -----------------------------------------
        u64 plo[8], phi[8];
        u64 sl = 0ull, sh = 0ull, ql = 0ull, qh = 0ull;
#pragma unroll
        for (int nt = 0; nt < 8; nt++) {
            u64 bp = b1v[nt * 4 + s4];
            u64 a = pk2(d1[t][nt][0], d1[t][nt][1]);
            u64 b = pk2(d1[t][nt][2], d1[t][nt][3]);
            ADD2(plo[nt], a, bp);
            ADD2(phi[nt], b, bp);
            ADD2(sl, sl, plo[nt]);
            FMA2(ql, plo[nt], plo[nt], ql);
            ADD2(sh, sh, phi[nt]);
            FMA2(qh, phi[nt], phi[nt], qh);
        }
        float2 fsl = unpk(sl), fsh = unpk(sh), fql = unpk(ql), fqh = unpk(qh);
        float slo = fsl.x + fsl.y, shi = fsh.x + fsh.y;
        float sqlo = fql.x + fql.y, sqhi = fqh.x + fqh.y;
#pragma unroll
        for (int d = 1; d <= 2; d <<= 1) {
            slo  += __shfl_xor_sync(0xffffffffu, slo, d);
            shi  += __shfl_xor_sync(0xffffffffu, shi, d);
            sqlo += __shfl_xor_sync(0xffffffffu, sqlo, d);
            sqhi += __shfl_xor_sync(0xffffffffu, sqhi, d);
        }
        float mulo = slo * (1.0f / 64.0f);
        float muhi = shi * (1.0f / 64.0f);
        float varlo = sqlo * (1.0f / 64.0f) - mulo * mulo;
        float varhi = sqhi * (1.0f / 64.0f) - muhi * muhi;
        float rstdlo = rsqrtf(varlo + 1e-5f);
        float rstdhi = rsqrtf(varhi + 1e-5f);
        u64 rl2 = pk2(rstdlo, rstdlo), rh2 = pk2(rstdhi, rstdhi);
        u64 nml = pk2(-mulo, -mulo), nmh = pk2(-muhi, -muhi);

        // ---- scale + GELU (folded bias) ------------------------------------------
#pragma unroll
        for (int nt = 0; nt < 8; nt++) {
            u64 gm = gmv[nt * 4 + s4], bt = btv[nt * 4 + s4];
            u64 grl; MUL2(grl, gm, rl2);
            u64 grh; MUL2(grh, gm, rh2);
            u64 btl; FMA2(btl, grl, nml, bt);
            u64 bth; FMA2(bth, grh, nmh, bt);
            FMA2(plo[nt], plo[nt], grl, btl);
            FMA2(phi[nt], phi[nt], grh, bth);
            plo[nt] = gelu2(plo[nt]);
            phi[nt] = gelu2(phi[nt]);
        }

        // ---- layer 2: per-k2 A-frag pack + MMA (1 term) ---------------------------
        float d2[4][4];
#pragma unroll
        for (int nt = 0; nt < 4; nt++)
#pragma unroll
            for (int j = 0; j < 4; j++) d2[nt][j] = 0.f;

#pragma unroll
        for (int k2 = 0; k2 < 4; k2++) {
            uint32_t A2[4];
            A2[0] = packh2p(plo[2 * k2]);
            A2[1] = packh2p(phi[2 * k2]);
            A2[2] = packh2p(plo[2 * k2 + 1]);
            A2[3] = packh2p(phi[2 * k2 + 1]);
            const uint2* bp2 = reinterpret_cast<const uint2*>(
                smu + B2F + ((k2 * 4 + s4) * 36 + q) * 2);
            uint2 bh[4];
#pragma unroll
            for (int nt = 0; nt < 4; nt++) bh[nt] = bp2[nt * 8];
#pragma unroll
            for (int nt = 0; nt < 4; nt++) mma_f16(d2[nt], A2, bh[nt].x, bh[nt].y);
        }

        // ---- bias + GELU on layer-2 output ----------------------------------------
        u64 qlo[4], qhi2[4];
#pragma unroll
        for (int nt = 0; nt < 4; nt++) {
            u64 bp = b2v[nt * 4 + s4];
            u64 a = pk2(d2[nt][0], d2[nt][1]);
            u64 b = pk2(d2[nt][2], d2[nt][3]);
            ADD2(a, a, bp);
            ADD2(b, b, bp);
            qlo[nt]  = gelu2(a);
            qhi2[nt] = gelu2(b);
        }

        // ---- merged heads -----------------------------------------------------------
        int growlo = warpRow + t * 16 + q;
        int growhi = growlo + 8;
        int rrlo = rrl[t], rrhi = rrh[t];
        const u64* wrlo = reinterpret_cast<const u64*>(par + P_WR + rrlo * 64);
        const u64* wrhi = reinterpret_cast<const u64*>(par + P_WR + rrhi * 64);
        const float* sglo = par + P_SG + rrlo * 36;
        const float* sghi = par + P_SG + rrhi * 36;

        u64 ca2lo = 0ull, cr2lo = 0ull, ca2hi = 0ull, cr2hi = 0ull;
#pragma unroll
        for (int nt = 0; nt < 4; nt++) {
            int ch = nt * 8 + s4 * 2;
            float2 h2  = unpk(qlo[nt]);
            float2 k2v = unpk(qhi2[nt]);
            float2 sl2 = *reinterpret_cast<const float2*>(sglo + ch);
            float2 sh2 = *reinterpret_cast<const float2*>(sghi + ch);
            float e0 = h2.x * sl2.x,  e1 = h2.y * sl2.y;
            float f0 = k2v.x * sh2.x, f1 = k2v.y * sh2.y;
            FMA2(ca2lo, pk2(e0, e0), wgv[ch],     ca2lo);
            FMA2(ca2lo, pk2(e1, e1), wgv[ch + 1], ca2lo);
            FMA2(cr2lo, pk2(h2.x, h2.x), wrlo[ch],     cr2lo);
            FMA2(cr2lo, pk2(h2.y, h2.y), wrlo[ch + 1], cr2lo);
            FMA2(ca2hi, pk2(f0, f0), wgv[ch],     ca2hi);
            FMA2(ca2hi, pk2(f1, f1), wgv[ch + 1], ca2hi);
            FMA2(cr2hi, pk2(k2v.x, k2v.x), wrhi[ch],     cr2hi);
            FMA2(cr2hi, pk2(k2v.y, k2v.y), wrhi[ch + 1], cr2hi);
        }
        float2 calo = unpk(ca2lo), crlo = unpk(cr2lo);
        float2 cahi = unpk(ca2hi), crhi = unpk(cr2hi);
#pragma unroll
        for (int d = 1; d <= 2; d <<= 1) {
            calo.x += __shfl_xor_sync(0xffffffffu, calo.x, d);
            calo.y += __shfl_xor_sync(0xffffffffu, calo.y, d);
            crlo.x += __shfl_xor_sync(0xffffffffu, crlo.x, d);
            crlo.y += __shfl_xor_sync(0xffffffffu, crlo.y, d);
            cahi.x += __shfl_xor_sync(0xffffffffu, cahi.x, d);
            cahi.y += __shfl_xor_sync(0xffffffffu, cahi.y, d);
            crhi.x += __shfl_xor_sync(0xffffffffu, crhi.x, d);
            crhi.y += __shfl_xor_sync(0xffffffffu, crhi.y, d);
        }

        if (s4 == 0) {
            const float bg0 = par[P_BG], bg1 = par[P_BG + 1];
            if (growlo < B) {
                float2 o;
                o.x = (calo.x + 0.3f * crlo.x + bg0 + par[P_BR + rrlo * 2]) * it;
                o.y = (calo.y + 0.3f * crlo.y + bg1 + par[P_BR + rrlo * 2 + 1]) * it;
                reinterpret_cast<float2*>(out)[growlo] = o;
            }
            if (growhi < B) {
                float2 o;
                o.x = (cahi.x + 0.3f * crhi.x + bg0 + par[P_BR + rrhi * 2]) * it;
                o.y = (cahi.y + 0.3f * crhi.y + bg1 + par[P_BR + rrhi * 2 + 1]) * it;
                reinterpret_cast<float2*>(out)[growhi] = o;
            }
        }
    }
}

extern "C" void kernel_launch(void* const* d_in, const int* in_sizes, int n_in,
                              void* d_out, int out_size)
{
    const float* x        = (const float*)d_in[0];
    const int*   regime   = (const int*)  d_in[1];
    const float* W1       = (const float*)d_in[2];
    const float* b1       = (const float*)d_in[3];
    const float* gamma    = (const float*)d_in[4];
    const float* beta     = (const float*)d_in[5];
    const float* W2       = (const float*)d_in[6];
    const float* b2       = (const float*)d_in[7];
    const float* Wg       = (const float*)d_in[8];
    const float* bg       = (const float*)d_in[9];
    const float* Wr       = (const float*)d_in[10];
    const float* br       = (const float*)d_in[11];
    const float* emb      = (const float*)d_in[12];
    const float* log_temp = (const float*)d_in[13];
    float* out = (float*)d_out;

    const int B = in_sizes[1];
    const int grid = (B + ROWS - 1) / ROWS;

    cudaFuncSetAttribute(nml_mma_kernel,
                         cudaFuncAttributeMaxDynamicSharedMemorySize, SMEM_BYTES);
    nml_mma_kernel<<<grid, TPB, SMEM_BYTES>>>(x, regime, W1, b1, gamma, beta,
                                              W2, b2, Wg, bg, Wr, br, emb,
                                              log_temp, out, B);
}